// round 6
// baseline (speedup 1.0000x reference)
#include <cuda_runtime.h>
#include <cuda_bf16.h>

// Problem constants
// B=4, C=512, H=W=64 -> N=4096, CI=256
#define NB   4
#define NC   512
#define NN_  4096
#define NCI  256

// ---------------------------------------------------------------------------
// Scratch (device globals: allocation inside kernel_launch is forbidden)
// ---------------------------------------------------------------------------
__device__ float g_w  [3 * NCI * NC];            // concat [w_phi; w_theta; w_g]  (768 x 512)
__device__ float g_ptg[NB * 3 * NCI * NN_];      // per batch: rows 0-255 phi, 256-511 theta, 512-767 g
__device__ float g_f  [(long long)NB * NN_ * NN_]; // attention scores / probs (268 MB)
__device__ float g_y  [NB * NCI * NN_];          // y = a @ g^T  (b, ci, N)

// ---------------------------------------------------------------------------
// Weight concat: one GEMM for all three projections
// ---------------------------------------------------------------------------
__global__ void concat_w_kernel(const float* __restrict__ a,
                                const float* __restrict__ b,
                                const float* __restrict__ c) {
    int i = blockIdx.x * 256 + threadIdx.x;   // 512 blocks * 256 = 131072 = 256*512
    g_w[i]           = a[i];
    g_w[i + 131072]  = b[i];
    g_w[i + 262144]  = c[i];
}

// ---------------------------------------------------------------------------
// Generic batched SGEMM, 128x128 block tile, BK=8, 8x8 per-thread fragments,
// double-buffered shared memory. Template params select operand layouts:
//   A_KC : A is (M,K) row-major (contraction contiguous). Else A is (K,M) rm.
//   B_NC : B is (K,N) row-major. Else B is (N,K) rm (contraction contiguous).
// All of M, Nn multiples of 128; K multiple of 8. No bounds checks needed.
// ---------------------------------------------------------------------------
template <bool A_KC, bool B_NC>
__global__ void __launch_bounds__(256)
sgemm128(const float* __restrict__ A, const float* __restrict__ B,
         float* __restrict__ C, int M, int Nn, int K,
         int lda, int ldb, int ldc,
         long long sA, long long sB, long long sC)
{
    __shared__ float As[2][8][132];
    __shared__ float Bs[2][8][132];

    const int t  = threadIdx.x;
    const int tx = t & 15;
    const int ty = t >> 4;

    A += (long long)blockIdx.z * sA;
    B += (long long)blockIdx.z * sB;
    C += (long long)blockIdx.z * sC;

    const int m0 = blockIdx.y * 128;
    const int n0 = blockIdx.x * 128;

    // Load-index mapping (each thread moves one float4 per operand per k-tile)
    int a_m, a_k, b_n, b_k;
    if (A_KC) { a_m = t >> 1;  a_k = (t & 1) * 4; }
    else      { a_k = t >> 5;  a_m = (t & 31) * 4; }
    if (B_NC) { b_k = t >> 5;  b_n = (t & 31) * 4; }
    else      { b_n = t >> 1;  b_k = (t & 1) * 4; }

    const float* Ag;
    if (A_KC) Ag = A + (long long)(m0 + a_m) * lda + a_k;
    else      Ag = A + (long long)a_k * lda + m0 + a_m;
    const float* Bg;
    if (B_NC) Bg = B + (long long)b_k * ldb + n0 + b_n;
    else      Bg = B + (long long)(n0 + b_n) * ldb + b_k;

    const long long aStep = A_KC ? 8LL : 8LL * lda;
    const long long bStep = B_NC ? 8LL * ldb : 8LL;

    // Prologue: stage tile 0
    float4 ra = *(const float4*)Ag;
    float4 rb = *(const float4*)Bg;
    if (A_KC) {
        As[0][a_k + 0][a_m] = ra.x; As[0][a_k + 1][a_m] = ra.y;
        As[0][a_k + 2][a_m] = ra.z; As[0][a_k + 3][a_m] = ra.w;
    } else {
        *(float4*)&As[0][a_k][a_m] = ra;
    }
    if (B_NC) {
        *(float4*)&Bs[0][b_k][b_n] = rb;
    } else {
        Bs[0][b_k + 0][b_n] = rb.x; Bs[0][b_k + 1][b_n] = rb.y;
        Bs[0][b_k + 2][b_n] = rb.z; Bs[0][b_k + 3][b_n] = rb.w;
    }
    __syncthreads();

    float acc[8][8];
#pragma unroll
    for (int i = 0; i < 8; i++)
#pragma unroll
        for (int j = 0; j < 8; j++) acc[i][j] = 0.0f;

    const int nT = K >> 3;
    int buf = 0;

    for (int kt = 0; kt < nT; kt++) {
        float4 na, nb;
        const bool has_next = (kt + 1 < nT);
        if (has_next) {
            Ag += aStep; Bg += bStep;
            na = *(const float4*)Ag;
            nb = *(const float4*)Bg;
        }
#pragma unroll
        for (int k = 0; k < 8; k++) {
            float af[8], bf[8];
            *(float4*)&af[0] = *(const float4*)&As[buf][k][ty * 8];
            *(float4*)&af[4] = *(const float4*)&As[buf][k][ty * 8 + 4];
            *(float4*)&bf[0] = *(const float4*)&Bs[buf][k][tx * 8];
            *(float4*)&bf[4] = *(const float4*)&Bs[buf][k][tx * 8 + 4];
#pragma unroll
            for (int i = 0; i < 8; i++)
#pragma unroll
                for (int j = 0; j < 8; j++)
                    acc[i][j] = fmaf(af[i], bf[j], acc[i][j]);
        }
        if (has_next) {
            const int nbuf = buf ^ 1;
            if (A_KC) {
                As[nbuf][a_k + 0][a_m] = na.x; As[nbuf][a_k + 1][a_m] = na.y;
                As[nbuf][a_k + 2][a_m] = na.z; As[nbuf][a_k + 3][a_m] = na.w;
            } else {
                *(float4*)&As[nbuf][a_k][a_m] = na;
            }
            if (B_NC) {
                *(float4*)&Bs[nbuf][b_k][b_n] = nb;
            } else {
                Bs[nbuf][b_k + 0][b_n] = nb.x; Bs[nbuf][b_k + 1][b_n] = nb.y;
                Bs[nbuf][b_k + 2][b_n] = nb.z; Bs[nbuf][b_k + 3][b_n] = nb.w;
            }
            __syncthreads();
            buf = nbuf;
        }
    }

    // Epilogue
#pragma unroll
    for (int i = 0; i < 8; i++) {
        long long row = (long long)(m0 + ty * 8 + i) * ldc + n0 + tx * 8;
        float4 c0 = make_float4(acc[i][0], acc[i][1], acc[i][2], acc[i][3]);
        float4 c1 = make_float4(acc[i][4], acc[i][5], acc[i][6], acc[i][7]);
        *(float4*)&C[row]     = c0;
        *(float4*)&C[row + 4] = c1;
    }
}

// ---------------------------------------------------------------------------
// Softmax over rows of 4096. Polynomial exp (7 FMA) instead of MUFU.EX2:
// EX2 is rt=8/SMSP on sm_103a -> only ~140G exp/s chip-wide; FMA path is ~25x.
// ---------------------------------------------------------------------------
__device__ __forceinline__ float fast_exp(float x) {
    float t = x * 1.4426950408889634f;       // x * log2(e), t <= 0 here
    t = fmaxf(t, -126.0f);
    float fi = floorf(t);
    float fr = (t - fi) * 0.6931471805599453f;   // fr in [0, ln2)
    float p = 1.0f / 720.0f;
    p = fmaf(p, fr, 1.0f / 120.0f);
    p = fmaf(p, fr, 1.0f / 24.0f);
    p = fmaf(p, fr, 1.0f / 6.0f);
    p = fmaf(p, fr, 0.5f);
    p = fmaf(p, fr, 1.0f);
    p = fmaf(p, fr, 1.0f);
    int n = (int)fi;
    return p * __int_as_float((n + 127) << 23);
}

__global__ void __launch_bounds__(256) softmax_kernel(float* __restrict__ f) {
    float* p = f + (long long)blockIdx.x * NN_;
    const int t = threadIdx.x;
    float v[16];
    float mx = -3.4e38f;
#pragma unroll
    for (int i = 0; i < 16; i++) {
        v[i] = p[i * 256 + t];               // coalesced: stride-256 per-thread subset
        mx = fmaxf(mx, v[i]);
    }
#pragma unroll
    for (int o = 16; o > 0; o >>= 1)
        mx = fmaxf(mx, __shfl_xor_sync(0xffffffffu, mx, o));
    __shared__ float sred[8];
    if ((t & 31) == 0) sred[t >> 5] = mx;
    __syncthreads();
#pragma unroll
    for (int i = 0; i < 8; i++) mx = fmaxf(mx, sred[i]);
    __syncthreads();                          // protect sred before reuse

    float s = 0.0f;
#pragma unroll
    for (int i = 0; i < 16; i++) { v[i] = fast_exp(v[i] - mx); s += v[i]; }
#pragma unroll
    for (int o = 16; o > 0; o >>= 1)
        s += __shfl_xor_sync(0xffffffffu, s, o);
    if ((t & 31) == 0) sred[t >> 5] = s;
    __syncthreads();
    s = 0.0f;
#pragma unroll
    for (int i = 0; i < 8; i++) s += sred[i];

    const float inv = 1.0f / s;
#pragma unroll
    for (int i = 0; i < 16; i++) p[i * 256 + t] = v[i] * inv;
}

// ---------------------------------------------------------------------------
// kernel_launch: graph-capturable (kernel launches only; no sync, no alloc)
// ---------------------------------------------------------------------------
extern "C" void kernel_launch(void* const* d_in, const int* in_sizes, int n_in,
                              void* d_out, int out_size) {
    (void)in_sizes; (void)n_in; (void)out_size;
    const float* x       = (const float*)d_in[0];
    const float* w_phi   = (const float*)d_in[1];
    const float* w_theta = (const float*)d_in[2];
    const float* w_g     = (const float*)d_in[3];
    const float* w_mask  = (const float*)d_in[4];
    float* out = (float*)d_out;

    float *wcat, *ptg, *f, *y;
    cudaGetSymbolAddress((void**)&wcat, g_w);
    cudaGetSymbolAddress((void**)&ptg,  g_ptg);
    cudaGetSymbolAddress((void**)&f,    g_f);
    cudaGetSymbolAddress((void**)&y,    g_y);

    // 1) concat projection weights -> one fused projection GEMM
    concat_w_kernel<<<512, 256>>>(w_phi, w_theta, w_g);

    // 2) [phi;theta;g] = Wcat(768x512) @ x[b](512x4096)   -> g_ptg (b,768,4096)
    sgemm128<true, true><<<dim3(32, 6, NB), 256>>>(
        wcat, x, ptg, 768, NN_, NC,
        NC, NN_, NN_, 0LL, (long long)NC * NN_, 768LL * NN_);

    // 3) f[n,m] = sum_c theta[c,n] * phi[c,m]   (TN: A is K-major)
    sgemm128<false, true><<<dim3(32, 32, NB), 256>>>(
        ptg + NCI * NN_, ptg, f, NN_, NN_, NCI,
        NN_, NN_, NN_, 768LL * NN_, 768LL * NN_, (long long)NN_ * NN_);

    // 4) softmax over last axis, in place
    softmax_kernel<<<NB * NN_, 256>>>(f);

    // 5) y[c,n] = sum_m g[c,m] * a[n,m]   (NT: B contraction-contiguous)
    sgemm128<true, false><<<dim3(32, 2, NB), 256>>>(
        ptg + 2 * NCI * NN_, f, y, NCI, NN_, NN_,
        NN_, NN_, NN_, 768LL * NN_, (long long)NN_ * NN_, (long long)NCI * NN_);

    // 6) out[o,n] = sum_c w_mask[o,c] * y[c,n]
    sgemm128<true, true><<<dim3(32, 4, NB), 256>>>(
        w_mask, y, out, NC, NN_, NCI,
        NCI, NN_, NN_, 0LL, (long long)NCI * NN_, (long long)NC * NN_);
}